// round 6
// baseline (speedup 1.0000x reference)
#include <cuda_runtime.h>
#include <cuda_fp16.h>
#include <math.h>

#define N 8192
#define M 8192
#define D 64
#define NIT 20

typedef unsigned long long ull;
typedef unsigned int uint;

static constexpr float EPS   = 0.05f;
static constexpr float ALPHA = 1.4426950408889634f;   // log2(e)
static constexpr float LN2   = 0.6931471805599453f;
static constexpr float KC    = (2.0f / 0.05f) * 1.4426950408889634f; // 57.7

// ---------------- scratch (device globals) ----------------
__device__ __half         dA16 [N * M];  // KC*(x@y^T) in fp16, row-major [i][j]
__device__ __half         dAT16[N * M];  // transpose [j][i]
__device__ unsigned char  dA8  [N * M];  // round(A/32)+128 (excess-128 int8)
__device__ unsigned char  dAT8 [N * M];
__device__ float  d_vt[N];
__device__ float  d_wt[M];
__device__ __half d_vt16[N];
__device__ __half d_wt16[M];
__device__ float  d_la[N];
__device__ float  d_lb[M];
__device__ float  d_x2[N];
__device__ float  d_y2[M];
__device__ float  d_an[N];
__device__ float  d_bn[M];
__device__ float  d_sums[2];

// ---------------- helpers ----------------
__device__ __forceinline__ float ex2(float x) {        // MUFU.EX2
    float r; asm("ex2.approx.f32 %0, %1;" : "=f"(r) : "f"(x)); return r;
}
__device__ __forceinline__ __half2 h2bits(uint u) {    // reinterpret bits as half2
    __half2 h; asm("mov.b32 %0, %1;" : "=r"(*(uint*)&h) : "r"(u)); return h;
}
__device__ __forceinline__ void fma2(ull& d, ull a, ull b) {
    asm("fma.rn.f32x2 %0, %1, %2, %0;" : "+l"(d) : "l"(a), "l"(b));
}
__device__ __forceinline__ ull bcast2(float a) {
    ull p; asm("mov.b64 %0, {%1, %1};" : "=l"(p) : "f"(a)); return p;
}
__device__ __forceinline__ void unpack2(ull p, float& lo, float& hi) {
    asm("mov.b64 {%0, %1}, %2;" : "=f"(lo), "=f"(hi) : "l"(p));
}
__device__ __forceinline__ ull pack2(float lo, float hi) {
    ull p; asm("mov.b64 %0, {%1, %2};" : "=l"(p) : "f"(lo), "f"(hi)); return p;
}
__device__ __forceinline__ uint qbyte(float v) {       // round(v/32) clamped, +128
    float f = fminf(fmaxf(v * 0.03125f, -127.f), 127.f);
    return (uint)(__float2int_rn(f) + 128);
}

// ---------------- row squared norms ----------------
__global__ void k_sqnorm(const float* __restrict__ X, const float* __restrict__ Y) {
    int w    = (blockIdx.x * blockDim.x + threadIdx.x) >> 5;
    int lane = threadIdx.x & 31;
    if (w >= N + M) return;
    const float* src = (w < N) ? (X + (size_t)w * D) : (Y + (size_t)(w - N) * D);
    float v0 = src[lane], v1 = src[lane + 32];
    float s = v0 * v0 + v1 * v1;
    #pragma unroll
    for (int off = 16; off; off >>= 1) s += __shfl_xor_sync(0xffffffffu, s, off);
    if (lane == 0) { if (w < N) d_x2[w] = s; else d_y2[w - N] = s; }
}

// ---------------- sums ----------------
__global__ void k_sum(const float* __restrict__ a, const float* __restrict__ b) {
    __shared__ float sa[1024], sb[1024];
    int t = threadIdx.x;
    float s1 = 0.f, s2 = 0.f;
    for (int i = t; i < N; i += 1024) s1 += a[i];
    for (int j = t; j < M; j += 1024) s2 += b[j];
    sa[t] = s1; sb[t] = s2; __syncthreads();
    for (int off = 512; off; off >>= 1) {
        if (t < off) { sa[t] += sa[t + off]; sb[t] += sb[t + off]; }
        __syncthreads();
    }
    if (t == 0) { d_sums[0] = sa[0]; d_sums[1] = sb[0]; }
}

// ---------------- init ----------------
__global__ void k_init(const float* __restrict__ a, const float* __restrict__ b) {
    int i = blockIdx.x * blockDim.x + threadIdx.x;
    if (i >= N) return;
    float lsa = logf(d_sums[0]), lsb = logf(d_sums[1]);
    float ai = a[i];
    d_la[i] = ALPHA * (logf(ai) - lsa);
    d_an[i] = ai / d_sums[0];
    float bi = b[i];
    float lb = ALPHA * (logf(bi) - lsb);
    d_lb[i] = lb;
    d_bn[i] = bi / d_sums[1];
    float w0 = lb - (ALPHA / EPS) * d_y2[i];
    d_wt[i]   = w0;
    d_wt16[i] = __float2half_rn(w0);
}

// ---------------- GEMM: 128x128 tile, 8x8/thread, emit fp16 + int8 ----------
__global__ void __launch_bounds__(256) gemm_kernel(const float* __restrict__ X,
                                                   const float* __restrict__ Y) {
    __shared__ __align__(16) char sbuf[34816];
    float*  sxT = (float*)sbuf;           // [32][132]
    float*  syT = sxT + 32 * 132;         // [32][132]
    __half* ts  = (__half*)sbuf;          // [128][136]

    int t  = threadIdx.x;
    int tx = t & 15, ty = t >> 4;
    int i0 = blockIdx.y * 128;
    int j0 = blockIdx.x * 128;

    ull acc[8][4];
    #pragma unroll
    for (int u = 0; u < 8; u++)
        #pragma unroll
        for (int v = 0; v < 4; v++) acc[u][v] = 0ull;

    #pragma unroll
    for (int k0 = 0; k0 < 64; k0 += 32) {
        if (k0) __syncthreads();
        #pragma unroll
        for (int it = 0; it < 4; it++) {
            int q = t + 256 * it;
            int r = q >> 3, c = q & 7;
            float4 fx = *reinterpret_cast<const float4*>(X + (size_t)(i0 + r) * D + k0 + c * 4);
            sxT[(c * 4 + 0) * 132 + r] = fx.x;
            sxT[(c * 4 + 1) * 132 + r] = fx.y;
            sxT[(c * 4 + 2) * 132 + r] = fx.z;
            sxT[(c * 4 + 3) * 132 + r] = fx.w;
            float4 fy = *reinterpret_cast<const float4*>(Y + (size_t)(j0 + r) * D + k0 + c * 4);
            syT[(c * 4 + 0) * 132 + r] = fy.x;
            syT[(c * 4 + 1) * 132 + r] = fy.y;
            syT[(c * 4 + 2) * 132 + r] = fy.z;
            syT[(c * 4 + 3) * 132 + r] = fy.w;
        }
        __syncthreads();

        #pragma unroll 8
        for (int k = 0; k < 32; k++) {
            float4 a0 = *reinterpret_cast<const float4*>(&sxT[k * 132 + ty * 8]);
            float4 a1 = *reinterpret_cast<const float4*>(&sxT[k * 132 + ty * 8 + 4]);
            float4 b0 = *reinterpret_cast<const float4*>(&syT[k * 132 + tx * 8]);
            float4 b1 = *reinterpret_cast<const float4*>(&syT[k * 132 + tx * 8 + 4]);
            ull bb0 = pack2(b0.x, b0.y), bb1 = pack2(b0.z, b0.w);
            ull bb2 = pack2(b1.x, b1.y), bb3 = pack2(b1.z, b1.w);
            float av[8] = {a0.x, a0.y, a0.z, a0.w, a1.x, a1.y, a1.z, a1.w};
            #pragma unroll
            for (int u = 0; u < 8; u++) {
                ull au = bcast2(av[u]);
                fma2(acc[u][0], au, bb0);
                fma2(acc[u][1], au, bb1);
                fma2(acc[u][2], au, bb2);
                fma2(acc[u][3], au, bb3);
            }
        }
    }

    __syncthreads();   // sxT/syT reads done; sbuf reused as ts below

    #pragma unroll
    for (int u = 0; u < 8; u++) {
        float v[8];
        #pragma unroll
        for (int p = 0; p < 4; p++) {
            float lo, hi; unpack2(acc[u][p], lo, hi);
            v[2 * p] = lo * KC; v[2 * p + 1] = hi * KC;
        }
        // fp16 store
        uint4 o;
        ((__half2*)&o)[0] = __floats2half2_rn(v[0], v[1]);
        ((__half2*)&o)[1] = __floats2half2_rn(v[2], v[3]);
        ((__half2*)&o)[2] = __floats2half2_rn(v[4], v[5]);
        ((__half2*)&o)[3] = __floats2half2_rn(v[6], v[7]);
        *reinterpret_cast<uint4*>(dA16 + (size_t)(i0 + ty * 8 + u) * M + j0 + tx * 8) = o;
        // int8 store
        uint2 pb;
        pb.x = qbyte(v[0]) | (qbyte(v[1]) << 8) | (qbyte(v[2]) << 16) | (qbyte(v[3]) << 24);
        pb.y = qbyte(v[4]) | (qbyte(v[5]) << 8) | (qbyte(v[6]) << 16) | (qbyte(v[7]) << 24);
        *reinterpret_cast<uint2*>(dA8 + (size_t)(i0 + ty * 8 + u) * M + j0 + tx * 8) = pb;
        // transpose stash (fp16)
        #pragma unroll
        for (int vv = 0; vv < 8; vv++)
            ts[(tx * 8 + vv) * 136 + ty * 8 + u] = __float2half_rn(v[vv]);
    }

    __syncthreads();
    #pragma unroll
    for (int it = 0; it < 8; it++) {
        int q = t + 256 * it;
        int jj = q >> 4, c = q & 15;
        uint4 o = *reinterpret_cast<const uint4*>(&ts[jj * 136 + c * 8]);
        *reinterpret_cast<uint4*>(dAT16 + (size_t)(j0 + jj) * N + i0 + c * 8) = o;
        // derive transposed int8 from the fp16 values (consistent with dAT16)
        const __half2* hp = (const __half2*)&o;
        uint qb[8];
        #pragma unroll
        for (int k = 0; k < 4; k++) {
            float2 f = __half22float2(hp[k]);
            qb[2 * k]     = qbyte(f.x);
            qb[2 * k + 1] = qbyte(f.y);
        }
        uint2 pb;
        pb.x = qb[0] | (qb[1] << 8) | (qb[2] << 16) | (qb[3] << 24);
        pb.y = qb[4] | (qb[5] << 8) | (qb[6] << 16) | (qb[7] << 24);
        *reinterpret_cast<uint2*>(dAT8 + (size_t)(j0 + jj) * N + i0 + c * 8) = pb;
    }
}

// ---------------- two-phase LSE pass: warp/row ----------------
// Phase 1: int8 stream, fp16 SIMD max per 64-elem group (no EX2, no branches).
// Phase 2: exact fp16+f32 sum over hot groups only, fixed m2.
template <bool ROWPASS>
__global__ void __launch_bounds__(256) pass_kernel() {
    __shared__ __align__(16) __half sw[8192];
    const unsigned char* __restrict__ M8   = ROWPASS ? dA8   : dAT8;
    const __half*        __restrict__ M16  = ROWPASS ? dA16  : dAT16;
    const float*         __restrict__ w32  = ROWPASS ? d_wt  : d_vt;
    const __half*        __restrict__ w16g = ROWPASS ? d_wt16 : d_vt16;
    const float*         __restrict__ lvec = ROWPASS ? d_la  : d_lb;
    float*   __restrict__ vout   = ROWPASS ? d_vt   : d_wt;
    __half*  __restrict__ vout16 = ROWPASS ? d_vt16 : d_wt16;

    int t = threadIdx.x;
    {   // fill w16 smem: 8192 halves = 1024 uint4
        const uint4* src = reinterpret_cast<const uint4*>(w16g);
        uint4* dst = reinterpret_cast<uint4*>(sw);
        #pragma unroll
        for (int it = 0; it < 4; it++) dst[t + 256 * it] = src[t + 256 * it];
    }
    __syncthreads();

    int warp = t >> 5, lane = t & 31;
    int row  = blockIdx.x * 8 + warp;
    const uint4* r8  = reinterpret_cast<const uint4*>(M8 + (size_t)row * M);
    const uint4* sw4 = reinterpret_cast<const uint4*>(sw);

    const __half2 H1152 = __floats2half2_rn(1152.f, 1152.f);  // bias: 1024 + 128
    const __half2 H32   = __floats2half2_rn(32.f, 32.f);
    __half2 gmax[4];
    #pragma unroll
    for (int g = 0; g < 4; g++) gmax[g] = __floats2half2_rn(-60000.f, -60000.f);

    // ---- phase 1 ----
    uint4 buf[2][4];
    #pragma unroll
    for (int k = 0; k < 4; k++) buf[0][k] = r8[k * 32 + lane];
    #pragma unroll
    for (int g = 0; g < 4; g++) {
        if (g < 3) {
            #pragma unroll
            for (int k = 0; k < 4; k++) buf[(g + 1) & 1][k] = r8[(g + 1) * 128 + k * 32 + lane];
        }
        __half2 mx = gmax[g];
        #pragma unroll
        for (int k = 0; k < 4; k++) {
            uint4 pk = buf[g & 1][k];
            int sidx = ((g * 4 + k) * 32 + lane) * 2;   // uint4 index into sw
            uint4 wa = sw4[sidx], wb = sw4[sidx + 1];
            const __half2* wha = (const __half2*)&wa;
            const __half2* whb = (const __half2*)&wb;
            uint wd[4] = {pk.x, pk.y, pk.z, pk.w};
            #pragma unroll
            for (int q = 0; q < 4; q++) {
                // bytes b -> fp16 bit pattern of (1024 + b): 0x64 high byte
                __half2 h2a = h2bits(__byte_perm(wd[q], 0x00640064u, 0x4140));
                __half2 h2b = h2bits(__byte_perm(wd[q], 0x00640064u, 0x4342));
                __half2 w2a = (q < 2) ? wha[2 * q]     : whb[2 * (q - 2)];
                __half2 w2b = (q < 2) ? wha[2 * q + 1] : whb[2 * (q - 2) + 1];
                __half2 ta = __hfma2(__hsub2(h2a, H1152), H32, w2a);
                __half2 tb = __hfma2(__hsub2(h2b, H1152), H32, w2b);
                mx = __hmax2(mx, __hmax2(ta, tb));
            }
        }
        gmax[g] = mx;
    }

    // row max (approx) across lanes
    __half2 gm = __hmax2(__hmax2(gmax[0], gmax[1]), __hmax2(gmax[2], gmax[3]));
    float rm = fmaxf(__low2float(gm), __high2float(gm));
    #pragma unroll
    for (int off = 16; off; off >>= 1)
        rm = fmaxf(rm, __shfl_xor_sync(0xffffffffu, rm, off));
    float thr = rm - 96.f;   // skip-safe margin
    float m2  = rm + 30.f;   // guaranteed >= true max

    // ---- phase 2 ----
    const __half* m16row = M16 + (size_t)row * M;
    float s = 0.f;
    #pragma unroll
    for (int g = 0; g < 4; g++) {
        float gmf = fmaxf(__low2float(gmax[g]), __high2float(gmax[g]));
        bool hot = gmf >= thr;
        if (__ballot_sync(0xffffffffu, hot)) {
            if (hot) {
                #pragma unroll
                for (int k = 0; k < 4; k++) {
                    int e0 = ((g * 4 + k) * 32 + lane) * 16;
                    uint4 ha = *reinterpret_cast<const uint4*>(m16row + e0);
                    uint4 hb = *reinterpret_cast<const uint4*>(m16row + e0 + 8);
                    const __half2* hpa = (const __half2*)&ha;
                    const __half2* hpb = (const __half2*)&hb;
                    float4 w0 = *reinterpret_cast<const float4*>(w32 + e0);
                    float4 w1 = *reinterpret_cast<const float4*>(w32 + e0 + 4);
                    float4 w2 = *reinterpret_cast<const float4*>(w32 + e0 + 8);
                    float4 w3 = *reinterpret_cast<const float4*>(w32 + e0 + 12);
                    float2 f;
                    f = __half22float2(hpa[0]); s += ex2(f.x + w0.x - m2) + ex2(f.y + w0.y - m2);
                    f = __half22float2(hpa[1]); s += ex2(f.x + w0.z - m2) + ex2(f.y + w0.w - m2);
                    f = __half22float2(hpa[2]); s += ex2(f.x + w1.x - m2) + ex2(f.y + w1.y - m2);
                    f = __half22float2(hpa[3]); s += ex2(f.x + w1.z - m2) + ex2(f.y + w1.w - m2);
                    f = __half22float2(hpb[0]); s += ex2(f.x + w2.x - m2) + ex2(f.y + w2.y - m2);
                    f = __half22float2(hpb[1]); s += ex2(f.x + w2.z - m2) + ex2(f.y + w2.w - m2);
                    f = __half22float2(hpb[2]); s += ex2(f.x + w3.x - m2) + ex2(f.y + w3.y - m2);
                    f = __half22float2(hpb[3]); s += ex2(f.x + w3.z - m2) + ex2(f.y + w3.w - m2);
                }
            }
        }
    }
    #pragma unroll
    for (int off = 16; off; off >>= 1)
        s += __shfl_xor_sync(0xffffffffu, s, off);
    if (lane == 0) {
        float r = lvec[row] - (m2 + log2f(s));
        vout[row]   = r;
        vout16[row] = __float2half_rn(r);
    }
}

// ---------------- final reduction ----------------
__global__ void k_final(float* __restrict__ out) {
    __shared__ float sm[1024];
    int t = threadIdx.x;
    float s = 0.f;
    for (int i = t; i < N; i += 1024)
        s += d_an[i] * (d_x2[i] + EPS * LN2 * (d_vt[i] - d_la[i]));
    for (int j = t; j < M; j += 1024)
        s += d_bn[j] * (d_y2[j] + EPS * LN2 * (d_wt[j] - d_lb[j]));
    sm[t] = s; __syncthreads();
    for (int off = 512; off; off >>= 1) {
        if (t < off) sm[t] += sm[t + off];
        __syncthreads();
    }
    if (t == 0) out[0] = sm[0];
}

// ---------------- launch ----------------
extern "C" void kernel_launch(void* const* d_in, const int* in_sizes, int n_in,
                              void* d_out, int out_size) {
    const float* a = (const float*)d_in[0];
    const float* x = (const float*)d_in[1];
    const float* b = (const float*)d_in[2];
    const float* y = (const float*)d_in[3];
    float* out = (float*)d_out;

    k_sqnorm<<<(N + M) / 8, 256>>>(x, y);
    k_sum<<<1, 1024>>>(a, b);
    k_init<<<N / 256, 256>>>(a, b);
    gemm_kernel<<<dim3(M / 128, N / 128), 256>>>(x, y);

    for (int it = 0; it < NIT; ++it) {
        pass_kernel<true ><<<N / 8, 256>>>();  // v from w (A)
        pass_kernel<false><<<M / 8, 256>>>();  // w from v (AT)
    }
    pass_kernel<true><<<N / 8, 256>>>();       // f_fin; g_fin == g_20
    k_final<<<1, 1024>>>(out);
}